// round 5
// baseline (speedup 1.0000x reference)
#include <cuda_runtime.h>

#define TT 32
#define BB 256
#define C1 64
#define C2 128
#define C3 256

// ---- device scratch (allocation-free) ----
__device__ float g_c1[BB*C1*64];
__device__ float g_s1c[BB*C1*64], g_s1v[BB*C1*64];
__device__ float g_s2c[BB*C2*36], g_s2v[BB*C2*36];
__device__ float g_pool[BB*C2*9];
__device__ float g_s3c[BB*C3], g_s3v[BB*C3];
__device__ float g_flat[TT*BB*C3];
__device__ float g_stcc[BB*C3], g_stcv[BB*C3];
__device__ float g_src[BB*C3], g_srv[BB*C3];
__device__ float g_r[2*BB*C3];
__device__ float g_sfc[BB*128], g_sfv[BB*128];
__device__ float g_w2t[576*C2];
__device__ float g_w3t[1152*C3];
__device__ float g_tcwt[3*C3*C3];
__device__ float g_recwt[C3*C3];
__device__ float g_fc1wt[C3*128];

typedef unsigned long long u64;
__device__ __forceinline__ u64 pk2(float lo, float hi){
    u64 r; asm("mov.b64 %0, {%1,%2};" : "=l"(r) : "f"(lo), "f"(hi)); return r;
}
__device__ __forceinline__ void upk2(u64 v, float &lo, float &hi){
    asm("mov.b64 {%0,%1}, %2;" : "=f"(lo), "=f"(hi) : "l"(v));
}
__device__ __forceinline__ u64 ffma2(u64 a, u64 b, u64 c){
    u64 d; asm("fma.rn.f32x2 %0, %1, %2, %3;" : "=l"(d) : "l"(a), "l"(b), "l"(c)); return d;
}
// CUBA-LIF; state = (cur, veff = vlt*(1-spike))
__device__ __forceinline__ float lifs(float z, float* cp, float* vp){
    float cur = 0.5f*(*cp) + z;
    float vlt = 0.75f*(*vp) + cur;
    bool s = vlt > 0.5f;
    *cp = cur; *vp = s ? 0.0f : vlt;
    return s ? 1.0f : 0.0f;
}

__global__ void k_zero(float* __restrict__ dout){
    int i0 = blockIdx.x*blockDim.x + threadIdx.x, st = gridDim.x*blockDim.x;
    for(int i=i0;i<BB*C1*64;i+=st){ g_s1c[i]=0.f; g_s1v[i]=0.f; }
    for(int i=i0;i<BB*C2*36;i+=st){ g_s2c[i]=0.f; g_s2v[i]=0.f; }
    for(int i=i0;i<BB*C3;i+=st){
        g_s3c[i]=0.f; g_s3v[i]=0.f; g_stcc[i]=0.f; g_stcv[i]=0.f;
        g_src[i]=0.f; g_srv[i]=0.f; g_r[i]=0.f; g_r[BB*C3+i]=0.f;
    }
    for(int i=i0;i<BB*128;i+=st){ g_sfc[i]=0.f; g_sfv[i]=0.f; }
    for(int i=i0;i<BB*2;i+=st) dout[i]=0.f;
}

__global__ void k_prep(const float* __restrict__ w2, const float* __restrict__ w3,
                       const float* __restrict__ tcw, const float* __restrict__ recw,
                       const float* __restrict__ fc1w){
    int i0 = blockIdx.x*blockDim.x + threadIdx.x, st = gridDim.x*blockDim.x;
    for(int i=i0;i<C2*576;i+=st){ int co=i/576, k=i-co*576; g_w2t[k*C2+co]=w2[i]; }
    for(int i=i0;i<C3*1152;i+=st){ int co=i/1152, k=i-co*1152; g_w3t[k*C3+co]=w3[i]; }
    for(int i=i0;i<3*C3*C3;i+=st){
        int j=i/(C3*C3), r=i-j*C3*C3, o=r/C3, k=r-o*C3;
        g_tcwt[j*C3*C3 + k*C3 + o]=tcw[i];
    }
    for(int i=i0;i<C3*C3;i+=st){ int o=i/C3, k=i-o*C3; g_recwt[k*C3+o]=recw[i]; }
    for(int i=i0;i<128*C3;i+=st){ int o=i/C3, k=i-o*C3; g_fc1wt[k*128+o]=fc1w[i]; }
}

// conv1: 1->64, 10x10 -> 8x8, + LIF. One block per image.
__global__ void k_conv1(const float* __restrict__ x, const float* __restrict__ w1,
                        const float* __restrict__ b1, int t){
    __shared__ float sx[100], sw[C1*9], sb[C1];
    int b = blockIdx.x, tid = threadIdx.x;
    if (tid < 100) sx[tid] = x[(b*100 + tid)*TT + t];
    for (int i=tid;i<C1*9;i+=256) sw[i] = w1[i];
    if (tid < C1) sb[tid] = b1[tid];
    __syncthreads();
    #pragma unroll
    for (int l=0;l<16;l++){
        int e = l*256 + tid;
        int c = e>>6, pos = e&63, i = pos>>3, j = pos&7;
        float z = sb[c];
        #pragma unroll
        for(int ki=0;ki<3;ki++)
            #pragma unroll
            for(int kj=0;kj<3;kj++)
                z += sw[c*9+ki*3+kj]*sx[(i+ki)*10 + j+kj];
        int idx = (b<<12) + e;
        g_c1[idx] = lifs(z, &g_s1c[idx], &g_s1v[idx]);
    }
}

// conv2: 64->128, 8x8 -> 6x6, FFMA2 packed fp32, + LIF + fused AvgPool2.
// 128 blocks x 2 images, 128 threads. Thread: 8 co x (3x3 quadrant of 6x6).
#define K2_SMEM (8192*8 + 2*C2*36*4)
__global__ __launch_bounds__(128) void k_conv2(const float* __restrict__ b2){
    extern __shared__ char smraw[];
    u64*   sc1 = (u64*)smraw;                      // [2][64][64] dup spikes
    float* sc2 = (float*)(smraw + 8192*8);         // [2][128][36] spikes
    int tid = threadIdx.x, b0 = blockIdx.x*2;
    for (int i=tid;i<8192;i+=128){ float v = g_c1[(b0<<12)+i]; sc1[i]=pk2(v,v); }
    __syncthreads();
    int h = tid>>6, lt = tid&63;
    int cog = lt>>2, quad = lt&3;
    int co0 = cog*8, oi0 = (quad>>1)*3, oj0 = (quad&1)*3;
    const u64* sc = sc1 + h*4096;

    float4 bb0 = *(const float4*)&b2[co0];
    float4 bb1 = *(const float4*)&b2[co0+4];
    u64 acc[4][9];
    u64 bp[4] = {pk2(bb0.x,bb0.y), pk2(bb0.z,bb0.w), pk2(bb1.x,bb1.y), pk2(bb1.z,bb1.w)};
    #pragma unroll
    for(int p=0;p<9;p++){ acc[0][p]=bp[0]; acc[1][p]=bp[1]; acc[2][p]=bp[2]; acc[3][p]=bp[3]; }

    for (int ci=0; ci<64; ci++){
        const u64* srow = sc + ci*64 + oi0*8 + oj0;
        const float4* wrow = (const float4*)(g_w2t + ci*9*C2 + co0);
        #pragma unroll
        for(int kk=0;kk<9;kk++){
            const int ki=kk/3, kj=kk-ki*3;
            u64 sp[9];
            #pragma unroll
            for(int di=0;di<3;di++)
                #pragma unroll
                for(int dj=0;dj<3;dj++)
                    sp[di*3+dj] = srow[(di+ki)*8 + dj+kj];
            float4 wa = wrow[kk*(C2/4)];
            float4 wb = wrow[kk*(C2/4)+1];
            u64 w0=pk2(wa.x,wa.y), w1=pk2(wa.z,wa.w);
            u64 w2u=pk2(wb.x,wb.y), w3u=pk2(wb.z,wb.w);
            #pragma unroll
            for(int p=0;p<9;p++){
                acc[0][p]=ffma2(w0 ,sp[p],acc[0][p]);
                acc[1][p]=ffma2(w1 ,sp[p],acc[1][p]);
                acc[2][p]=ffma2(w2u,sp[p],acc[2][p]);
                acc[3][p]=ffma2(w3u,sp[p],acc[3][p]);
            }
        }
    }
    __syncthreads();                  // done reading sc1; reuse as z-staging
    float* zbuf = (float*)sc1;        // [2][128][36]
    #pragma unroll
    for(int cp=0;cp<4;cp++)
        #pragma unroll
        for(int p=0;p<9;p++){
            float z0,z1; upk2(acc[cp][p], z0, z1);
            int di=p/3, dj=p-di*3, pidx=(oi0+di)*6 + (oj0+dj);
            zbuf[(h*C2 + co0+2*cp  )*36 + pidx] = z0;
            zbuf[(h*C2 + co0+2*cp+1)*36 + pidx] = z1;
        }
    __syncthreads();
    for(int i=tid;i<2*C2*36;i+=128){
        int gidx = b0*C2*36 + i;
        sc2[i] = lifs(zbuf[i], &g_s2c[gidx], &g_s2v[gidx]);
    }
    __syncthreads();
    for(int i=tid;i<2*C2*9;i+=128){
        int hh = i/(C2*9), rem = i - hh*(C2*9);
        int c = rem/9, pp = rem-c*9, pi = pp/3, pj = pp-pi*3;
        const float* s2 = sc2 + (hh*C2 + c)*36;
        g_pool[b0*C2*9 + i] = 0.25f*(s2[(2*pi)*6+2*pj] + s2[(2*pi)*6+2*pj+1]
                                   + s2[(2*pi+1)*6+2*pj] + s2[(2*pi+1)*6+2*pj+1]);
    }
}

// conv3 fc-style K=1152 + LIF -> flat spikes. 128 blocks = 32 img-groups(4) x ... 
// grid: blk>>1 = img-group (64 groups of 4), blk&1 = co half. 256 threads.
__global__ void k_conv3(const float* __restrict__ b3, int t){
    __shared__ float sp[4*1152];
    int blk = blockIdx.x, b0 = (blk>>1)*4, coh = (blk&1)*128, tid = threadIdx.x;
    for(int i=tid;i<4608;i+=256) sp[i] = g_pool[b0*1152 + i];
    __syncthreads();
    int bl = tid>>6, cg = tid&63;
    int b = b0+bl, co = coh + cg*2;
    const float* s = sp + bl*1152;
    const float* w = g_w3t + co;
    float a0=b3[co], a1=b3[co+1];
    #pragma unroll 4
    for(int k=0;k<1152;k++){
        float sv = s[k];
        float2 wv = *(const float2*)(w + k*C3);
        a0 += wv.x*sv; a1 += wv.y*sv;
    }
    int idx = b*C3 + co;
    float o0 = lifs(a0, &g_s3c[idx],   &g_s3v[idx]);
    float o1 = lifs(a1, &g_s3c[idx+1], &g_s3v[idx+1]);
    g_flat[t*BB*C3 + idx]   = o0;
    g_flat[t*BB*C3 + idx+1] = o1;
}

// fused tail: temporal-conv psp + LIF, recurrent + LIF, fc1 + LIF, fc2 accum.
// 64 blocks x 4 images, 256 threads.
__global__ void k_tail(const float* __restrict__ tcb, const float* __restrict__ recb,
                       const float* __restrict__ fc1b, const float* __restrict__ fc2w,
                       const float* __restrict__ tsw, float* __restrict__ dout,
                       int t, int nb){
    __shared__ float sf[3][4*C3], srp[4*C3], stc_s[4*C3], sr_s[4*C3], f1_s[4*128];
    int b0 = blockIdx.x*4, tid = threadIdx.x;
    for(int j=0;j<nb;j++){
        const float* fl = g_flat + (t-(nb-1)+j)*BB*C3 + b0*C3;
        for(int i=tid;i<4*C3;i+=256) sf[j][i]=fl[i];
    }
    { const float* rp = g_r + ((t+1)&1)*BB*C3 + b0*C3;
      for(int i=tid;i<4*C3;i+=256) srp[i]=rp[i]; }
    __syncthreads();
    int img = tid>>6, c0 = (tid&63)*4;
    int b = b0 + img;
    // tc psp
    float a[4];
    #pragma unroll
    for(int cc=0;cc<4;cc++){ a[cc]=0.f; for(int j=0;j<nb;j++) a[cc]+=tcb[j*C3+c0+cc]; }
    for(int j=0;j<nb;j++){
        const float* fl = sf[j] + img*C3;
        const float* w  = g_tcwt + j*C3*C3 + c0;
        #pragma unroll 4
        for(int k=0;k<C3;k++){
            float sv = fl[k];
            float4 wv = *(const float4*)(w + k*C3);
            a[0]+=wv.x*sv; a[1]+=wv.y*sv; a[2]+=wv.z*sv; a[3]+=wv.w*sv;
        }
    }
    #pragma unroll
    for(int cc=0;cc<4;cc++){
        int gi = b*C3 + c0 + cc;
        stc_s[img*C3 + c0 + cc] = lifs(a[cc], &g_stcc[gi], &g_stcv[gi]);
    }
    __syncthreads();
    // recurrent
    #pragma unroll
    for(int cc=0;cc<4;cc++) a[cc] = stc_s[img*C3+c0+cc] + recb[c0+cc];
    {
        const float* rp = srp + img*C3;
        const float* w  = g_recwt + c0;
        #pragma unroll 4
        for(int k=0;k<C3;k++){
            float sv = rp[k];
            float4 wv = *(const float4*)(w + k*C3);
            a[0]+=wv.x*sv; a[1]+=wv.y*sv; a[2]+=wv.z*sv; a[3]+=wv.w*sv;
        }
    }
    #pragma unroll
    for(int cc=0;cc<4;cc++){
        int gi = b*C3 + c0 + cc;
        float rs = lifs(a[cc], &g_src[gi], &g_srv[gi]);
        sr_s[img*C3 + c0 + cc] = rs;
        g_r[(t&1)*BB*C3 + gi] = rs;
    }
    __syncthreads();
    // fc1
    int o0 = (tid&63)*2;
    float f0 = fc1b[o0], f1v = fc1b[o0+1];
    {
        const float* rp = sr_s + img*C3;
        const float* w  = g_fc1wt + o0;
        #pragma unroll 4
        for(int k=0;k<C3;k++){
            float sv = rp[k];
            float2 wv = *(const float2*)(w + k*128);
            f0 += wv.x*sv; f1v += wv.y*sv;
        }
    }
    { int gi = b*128 + o0;
      f1_s[img*128 + o0]   = lifs(f0,  &g_sfc[gi],   &g_sfv[gi]);
      f1_s[img*128 + o0+1] = lifs(f1v, &g_sfc[gi+1], &g_sfv[gi+1]); }
    __syncthreads();
    // fc2 accumulate
    if (tid < 8){
        int im = tid>>1, o = tid&1;
        const float* f = f1_s + im*128;
        float s = 0.f;
        #pragma unroll 4
        for(int k=0;k<128;k++) s += f[k]*fc2w[o*128+k];
        dout[(b0+im)*2 + o] += s * tsw[t];
    }
}

extern "C" void kernel_launch(void* const* d_in, const int* in_sizes, int n_in,
                              void* d_out, int out_size){
    const float* x    = (const float*)d_in[0];
    const float* w1   = (const float*)d_in[1];
    const float* b1   = (const float*)d_in[2];
    const float* w2   = (const float*)d_in[3];
    const float* b2   = (const float*)d_in[4];
    const float* w3   = (const float*)d_in[5];
    const float* b3   = (const float*)d_in[6];
    const float* tcw  = (const float*)d_in[7];
    const float* tcb  = (const float*)d_in[8];
    const float* recw = (const float*)d_in[9];
    const float* recb = (const float*)d_in[10];
    const float* fc1w = (const float*)d_in[11];
    const float* fc1b = (const float*)d_in[12];
    const float* fc2w = (const float*)d_in[13];
    const float* tsw  = (const float*)d_in[14];
    float* out = (float*)d_out;

    static bool attr_set = false;
    if (!attr_set){
        cudaFuncSetAttribute(k_conv2, cudaFuncAttributeMaxDynamicSharedMemorySize, K2_SMEM);
        attr_set = true;
    }

    k_zero<<<256,256>>>(out);
    k_prep<<<256,256>>>(w2, w3, tcw, recw, fc1w);
    for (int t=0; t<TT; t++){
        int nb = t+1 < 3 ? t+1 : 3;
        k_conv1<<<256,256>>>(x, w1, b1, t);
        k_conv2<<<128,128,K2_SMEM>>>(b2);
        k_conv3<<<128,256>>>(b3, t);
        k_tail<<<64,256>>>(tcb, recb, fc1b, fc2w, tsw, out, t, nb);
    }
}

// round 6
// speedup vs baseline: 1.2263x; 1.2263x over previous
#include <cuda_runtime.h>

#define TT 32
#define BB 256
#define C1 64
#define C2 128
#define C3 256

// ---- device scratch (allocation-free) ----
__device__ float g_s1c[BB*C1*64], g_s1v[BB*C1*64];
__device__ float g_s2c[BB*C2*36], g_s2v[BB*C2*36];
__device__ float g_pool[BB*C2*9];
__device__ float g_s3c[BB*C3], g_s3v[BB*C3];
__device__ float g_flat[TT*BB*C3];
__device__ float g_stcc[BB*C3], g_stcv[BB*C3];
__device__ float g_src[BB*C3], g_srv[BB*C3];
__device__ float g_r[2*BB*C3];
__device__ float g_sfc[BB*128], g_sfv[BB*128];
__device__ float g_w2t[576*C2];
__device__ float g_w3t[1152*C3];
__device__ float g_tcwt[3*C3*C3];
__device__ float g_recwt[C3*C3];
__device__ float g_fc1wt[C3*128];

typedef unsigned long long u64;
__device__ __forceinline__ u64 pk2(float lo, float hi){
    u64 r; asm("mov.b64 %0, {%1,%2};" : "=l"(r) : "f"(lo), "f"(hi)); return r;
}
__device__ __forceinline__ void upk2(u64 v, float &lo, float &hi){
    asm("mov.b64 {%0,%1}, %2;" : "=f"(lo), "=f"(hi) : "l"(v));
}
__device__ __forceinline__ u64 ffma2(u64 a, u64 b, u64 c){
    u64 d; asm("fma.rn.f32x2 %0, %1, %2, %3;" : "=l"(d) : "l"(a), "l"(b), "l"(c)); return d;
}
// CUBA-LIF; state = (cur, veff = vlt*(1-spike))
__device__ __forceinline__ float lifs(float z, float* cp, float* vp){
    float cur = 0.5f*(*cp) + z;
    float vlt = 0.75f*(*vp) + cur;
    bool s = vlt > 0.5f;
    *cp = cur; *vp = s ? 0.0f : vlt;
    return s ? 1.0f : 0.0f;
}

__global__ void k_zero(float* __restrict__ dout){
    int i0 = blockIdx.x*blockDim.x + threadIdx.x, st = gridDim.x*blockDim.x;
    for(int i=i0;i<BB*C1*64;i+=st){ g_s1c[i]=0.f; g_s1v[i]=0.f; }
    for(int i=i0;i<BB*C2*36;i+=st){ g_s2c[i]=0.f; g_s2v[i]=0.f; }
    for(int i=i0;i<BB*C3;i+=st){
        g_s3c[i]=0.f; g_s3v[i]=0.f; g_stcc[i]=0.f; g_stcv[i]=0.f;
        g_src[i]=0.f; g_srv[i]=0.f; g_r[i]=0.f; g_r[BB*C3+i]=0.f;
    }
    for(int i=i0;i<BB*128;i+=st){ g_sfc[i]=0.f; g_sfv[i]=0.f; }
    for(int i=i0;i<BB*2;i+=st) dout[i]=0.f;
}

__global__ void k_prep(const float* __restrict__ w2, const float* __restrict__ w3,
                       const float* __restrict__ tcw, const float* __restrict__ recw,
                       const float* __restrict__ fc1w){
    int i0 = blockIdx.x*blockDim.x + threadIdx.x, st = gridDim.x*blockDim.x;
    for(int i=i0;i<C2*576;i+=st){ int co=i/576, k=i-co*576; g_w2t[k*C2+co]=w2[i]; }
    for(int i=i0;i<C3*1152;i+=st){ int co=i/1152, k=i-co*1152; g_w3t[k*C3+co]=w3[i]; }
    for(int i=i0;i<3*C3*C3;i+=st){
        int j=i/(C3*C3), r=i-j*C3*C3, o=r/C3, k=r-o*C3;
        g_tcwt[j*C3*C3 + k*C3 + o]=tcw[i];
    }
    for(int i=i0;i<C3*C3;i+=st){ int o=i/C3, k=i-o*C3; g_recwt[k*C3+o]=recw[i]; }
    for(int i=i0;i<128*C3;i+=st){ int o=i/C3, k=i-o*C3; g_fc1wt[k*128+o]=fc1w[i]; }
}

// ===== fused conv1 + conv2 + LIF + avgpool =====
// 128 blocks x 2 images, 256 threads (8 warps).
// Thread: 4 co x (3x3 quadrant of 6x6). Weights double-buffered via smem.
// smem: u64 sc1[8192] (dup spikes, 64KB) | float sw[2][8*9*128] (72KB)
#define K2_CH    8                       // ci per weight chunk
#define K2_CHF   (K2_CH*9*C2)            // floats per chunk = 9216
#define K2_SMEM  (8192*8 + 2*K2_CHF*4)   // 139264 B

__global__ __launch_bounds__(256) void k_conv12(const float* __restrict__ x,
                                                const float* __restrict__ w1,
                                                const float* __restrict__ b1,
                                                const float* __restrict__ b2, int t){
    extern __shared__ char smraw[];
    u64*   sc1 = (u64*)smraw;                         // [2][64][64] duplicated spikes
    float* sw  = (float*)(smraw + 8192*8);            // [2][K2_CHF]
    __shared__ float sx[200];
    int tid = threadIdx.x, b0 = blockIdx.x*2;

    // ---- conv1 (1->64, 10x10 -> 8x8) + LIF, spikes -> duplicated smem ----
    if (tid < 200){
        int im = tid/100, p = tid-100*im;
        sx[tid] = x[((b0+im)*100 + p)*TT + t];
    }
    __syncthreads();
    #pragma unroll 4
    for (int l=0; l<32; l++){
        int i = l*256 + tid;
        int im = i>>12, e = i&4095;
        int c = e>>6, pos = e&63, ii = pos>>3, jj = pos&7;
        float z = __ldg(&b1[c]);
        const float* wp = w1 + c*9;
        const float* xp = sx + im*100 + ii*10 + jj;
        #pragma unroll
        for(int ki=0;ki<3;ki++)
            #pragma unroll
            for(int kj=0;kj<3;kj++)
                z += __ldg(&wp[ki*3+kj]) * xp[ki*10+kj];
        int gidx = ((b0+im)<<12) + e;
        float v = lifs(z, &g_s1c[gidx], &g_s1v[gidx]);
        sc1[i] = pk2(v,v);
    }

    // ---- conv2 mainloop ----
    int h   = tid>>7, lt = tid&127;
    int cog = lt>>2, quad = lt&3;
    int co0 = cog*4;
    int oi0 = (quad>>1)*3, oj0 = (quad&1)*3;
    const u64* scb = sc1 + h*4096;

    float4 bb = *(const float4*)&b2[co0];
    u64 acc[2][9];
    {
        u64 p0 = pk2(bb.x,bb.y), p1 = pk2(bb.z,bb.w);
        #pragma unroll
        for(int p=0;p<9;p++){ acc[0][p]=p0; acc[1][p]=p1; }
    }

    float4 pre[9];
    // prologue: chunk 0 -> buf 0
    {
        const float4* src = (const float4*)g_w2t + tid;
        #pragma unroll
        for(int j=0;j<9;j++) pre[j] = src[j*256];
    }
    __syncthreads();   // also covers conv1 spike writes before window reads
    {
        float4* dst = (float4*)sw + tid;
        #pragma unroll
        for(int j=0;j<9;j++) dst[j*256] = pre[j];
    }
    __syncthreads();

    for (int ch=0; ch<64/K2_CH; ch++){
        if (ch < 64/K2_CH - 1){
            const float4* src = (const float4*)g_w2t + (ch+1)*(K2_CHF/4) + tid;
            #pragma unroll
            for(int j=0;j<9;j++) pre[j] = src[j*256];
        }
        const float* wbuf = sw + (ch&1)*K2_CHF;
        #pragma unroll 2
        for (int cl=0; cl<K2_CH; cl++){
            int ci = ch*K2_CH + cl;
            u64 win[25];
            const u64* wr = scb + ci*64 + oi0*8 + oj0;
            #pragma unroll
            for(int di=0;di<5;di++)
                #pragma unroll
                for(int dj=0;dj<5;dj++)
                    win[di*5+dj] = wr[di*8+dj];
            #pragma unroll
            for(int kk=0;kk<9;kk++){
                const int ki = kk/3, kj = kk - ki*3;
                float4 wv = *(const float4*)&wbuf[(cl*9+kk)*C2 + co0];
                u64 w0 = pk2(wv.x,wv.y), w1p = pk2(wv.z,wv.w);
                #pragma unroll
                for(int p=0;p<9;p++){
                    const int pi = p/3, pj = p - pi*3;
                    u64 s = win[(pi+ki)*5 + (pj+kj)];
                    acc[0][p] = ffma2(w0,  s, acc[0][p]);
                    acc[1][p] = ffma2(w1p, s, acc[1][p]);
                }
            }
        }
        if (ch < 64/K2_CH - 1){
            float4* dst = (float4*)(sw + ((ch+1)&1)*K2_CHF) + tid;
            #pragma unroll
            for(int j=0;j<9;j++) dst[j*256] = pre[j];
        }
        __syncthreads();
    }

    // ---- epilogue: z -> smem, LIF, avgpool ----
    float* zbuf = (float*)sc1;          // [2][128][36] (36KB <= 64KB)
    #pragma unroll
    for(int cp=0;cp<2;cp++)
        #pragma unroll
        for(int p=0;p<9;p++){
            float z0,z1; upk2(acc[cp][p], z0, z1);
            int di=p/3, dj=p-di*3, pidx=(oi0+di)*6 + (oj0+dj);
            zbuf[(h*C2 + co0+2*cp  )*36 + pidx] = z0;
            zbuf[(h*C2 + co0+2*cp+1)*36 + pidx] = z1;
        }
    __syncthreads();
    float* sc2 = sw;                    // reuse weight smem (36KB <= 72KB)
    for(int i=tid;i<2*C2*36;i+=256){
        int gidx = b0*C2*36 + i;
        sc2[i] = lifs(zbuf[i], &g_s2c[gidx], &g_s2v[gidx]);
    }
    __syncthreads();
    for(int i=tid;i<2*C2*9;i+=256){
        int hh = i/(C2*9), rem = i - hh*(C2*9);
        int c = rem/9, pp = rem-c*9, pi = pp/3, pj = pp-pi*3;
        const float* s2 = sc2 + (hh*C2 + c)*36;
        g_pool[b0*C2*9 + i] = 0.25f*(s2[(2*pi)*6+2*pj] + s2[(2*pi)*6+2*pj+1]
                                   + s2[(2*pi+1)*6+2*pj] + s2[(2*pi+1)*6+2*pj+1]);
    }
}

// ===== conv3 fc-style K=1152 + LIF -> flat spikes =====
// 128 blocks = 64 groups(4 img) x 2 co-halves. 256 threads:
// img = tid>>6; within img: 32 threads x 4co x K-half, pair-reduced via smem.
__global__ __launch_bounds__(256) void k_conv3(const float* __restrict__ b3, int t){
    __shared__ float sp[4*1152];
    __shared__ float red[256*4];
    int blk = blockIdx.x, b0 = (blk>>1)*4, coh = (blk&1)*128, tid = threadIdx.x;
    for(int i=tid;i<4608;i+=256) sp[i] = g_pool[b0*1152 + i];
    __syncthreads();
    int img = tid>>6, l = tid&63;
    int co  = coh + (l&31)*4;
    int kh  = l>>5;
    const float* s = sp + img*1152 + kh*576;
    const float* w = g_w3t + (kh*576)*C3 + co;
    float a0=0.f,a1=0.f,a2=0.f,a3=0.f;
    #pragma unroll 8
    for(int k=0;k<576;k++){
        float sv = s[k];
        float4 wv = *(const float4*)(w + k*C3);
        a0 += wv.x*sv; a1 += wv.y*sv; a2 += wv.z*sv; a3 += wv.w*sv;
    }
    red[tid*4+0]=a0; red[tid*4+1]=a1; red[tid*4+2]=a2; red[tid*4+3]=a3;
    __syncthreads();
    if (kh == 0){
        int pt = (tid+32)*4;
        a0 += red[pt+0]; a1 += red[pt+1]; a2 += red[pt+2]; a3 += red[pt+3];
        float4 bv = *(const float4*)&b3[co];
        a0 += bv.x; a1 += bv.y; a2 += bv.z; a3 += bv.w;
        int b = b0 + img;
        int idx = b*C3 + co;
        float4 o;
        o.x = lifs(a0, &g_s3c[idx+0], &g_s3v[idx+0]);
        o.y = lifs(a1, &g_s3c[idx+1], &g_s3v[idx+1]);
        o.z = lifs(a2, &g_s3c[idx+2], &g_s3v[idx+2]);
        o.w = lifs(a3, &g_s3c[idx+3], &g_s3v[idx+3]);
        *(float4*)&g_flat[t*BB*C3 + idx] = o;
    }
}

// ===== fused tail: temporal-conv + LIF, recurrent + LIF, fc1 + LIF, fc2 accum =====
// 64 blocks x 4 images, 256 threads.
__global__ void k_tail(const float* __restrict__ tcb, const float* __restrict__ recb,
                       const float* __restrict__ fc1b, const float* __restrict__ fc2w,
                       const float* __restrict__ tsw, float* __restrict__ dout,
                       int t, int nb){
    __shared__ float sf[3][4*C3], srp[4*C3], stc_s[4*C3], sr_s[4*C3], f1_s[4*128];
    int b0 = blockIdx.x*4, tid = threadIdx.x;
    for(int j=0;j<nb;j++){
        const float* fl = g_flat + (t-(nb-1)+j)*BB*C3 + b0*C3;
        for(int i=tid;i<4*C3;i+=256) sf[j][i]=fl[i];
    }
    { const float* rp = g_r + ((t+1)&1)*BB*C3 + b0*C3;
      for(int i=tid;i<4*C3;i+=256) srp[i]=rp[i]; }
    __syncthreads();
    int img = tid>>6, c0 = (tid&63)*4;
    int b = b0 + img;
    // temporal-conv psp
    float a[4];
    #pragma unroll
    for(int cc=0;cc<4;cc++){ a[cc]=0.f; for(int j=0;j<nb;j++) a[cc]+=tcb[j*C3+c0+cc]; }
    for(int j=0;j<nb;j++){
        const float* fl = sf[j] + img*C3;
        const float* w  = g_tcwt + j*C3*C3 + c0;
        #pragma unroll 8
        for(int k=0;k<C3;k++){
            float sv = fl[k];
            float4 wv = *(const float4*)(w + k*C3);
            a[0]+=wv.x*sv; a[1]+=wv.y*sv; a[2]+=wv.z*sv; a[3]+=wv.w*sv;
        }
    }
    #pragma unroll
    for(int cc=0;cc<4;cc++){
        int gi = b*C3 + c0 + cc;
        stc_s[img*C3 + c0 + cc] = lifs(a[cc], &g_stcc[gi], &g_stcv[gi]);
    }
    __syncthreads();
    // recurrent
    #pragma unroll
    for(int cc=0;cc<4;cc++) a[cc] = stc_s[img*C3+c0+cc] + recb[c0+cc];
    {
        const float* rp = srp + img*C3;
        const float* w  = g_recwt + c0;
        #pragma unroll 8
        for(int k=0;k<C3;k++){
            float sv = rp[k];
            float4 wv = *(const float4*)(w + k*C3);
            a[0]+=wv.x*sv; a[1]+=wv.y*sv; a[2]+=wv.z*sv; a[3]+=wv.w*sv;
        }
    }
    #pragma unroll
    for(int cc=0;cc<4;cc++){
        int gi = b*C3 + c0 + cc;
        float rs = lifs(a[cc], &g_src[gi], &g_srv[gi]);
        sr_s[img*C3 + c0 + cc] = rs;
        g_r[(t&1)*BB*C3 + gi] = rs;
    }
    __syncthreads();
    // fc1
    int o0 = (tid&63)*2;
    float f0 = fc1b[o0], f1v = fc1b[o0+1];
    {
        const float* rp = sr_s + img*C3;
        const float* w  = g_fc1wt + o0;
        #pragma unroll 8
        for(int k=0;k<C3;k++){
            float sv = rp[k];
            float2 wv = *(const float2*)(w + k*128);
            f0 += wv.x*sv; f1v += wv.y*sv;
        }
    }
    { int gi = b*128 + o0;
      f1_s[img*128 + o0]   = lifs(f0,  &g_sfc[gi],   &g_sfv[gi]);
      f1_s[img*128 + o0+1] = lifs(f1v, &g_sfc[gi+1], &g_sfv[gi+1]); }
    __syncthreads();
    // fc2 accumulate
    if (tid < 8){
        int im = tid>>1, o = tid&1;
        const float* f = f1_s + im*128;
        float s = 0.f;
        #pragma unroll 8
        for(int k=0;k<128;k++) s += f[k]*fc2w[o*128+k];
        dout[(b0+im)*2 + o] += s * tsw[t];
    }
}

extern "C" void kernel_launch(void* const* d_in, const int* in_sizes, int n_in,
                              void* d_out, int out_size){
    const float* x    = (const float*)d_in[0];
    const float* w1   = (const float*)d_in[1];
    const float* b1   = (const float*)d_in[2];
    const float* w2   = (const float*)d_in[3];
    const float* b2   = (const float*)d_in[4];
    const float* w3   = (const float*)d_in[5];
    const float* b3   = (const float*)d_in[6];
    const float* tcw  = (const float*)d_in[7];
    const float* tcb  = (const float*)d_in[8];
    const float* recw = (const float*)d_in[9];
    const float* recb = (const float*)d_in[10];
    const float* fc1w = (const float*)d_in[11];
    const float* fc1b = (const float*)d_in[12];
    const float* fc2w = (const float*)d_in[13];
    const float* tsw  = (const float*)d_in[14];
    float* out = (float*)d_out;

    cudaFuncSetAttribute(k_conv12, cudaFuncAttributeMaxDynamicSharedMemorySize, K2_SMEM);

    k_zero<<<256,256>>>(out);
    k_prep<<<256,256>>>(w2, w3, tcw, recw, fc1w);
    for (int t=0; t<TT; t++){
        int nb = t+1 < 3 ? t+1 : 3;
        k_conv12<<<128,256,K2_SMEM>>>(x, w1, b1, b2, t);
        k_conv3<<<128,256>>>(b3, t);
        k_tail<<<64,256>>>(tcb, recb, fc1b, fc2w, tsw, out, t, nb);
    }
}

// round 7
// speedup vs baseline: 2.4067x; 1.9625x over previous
#include <cuda_runtime.h>

#define TT 32
#define BB 256
#define C1 64
#define C2 128
#define C3 256

// ---- device scratch (allocation-free) ----
__device__ float g_s1c[BB*C1*64], g_s1v[BB*C1*64];
__device__ float g_s2c[BB*C2*36], g_s2v[BB*C2*36];
__device__ float g_pool[BB*C2*9];
__device__ float g_s3c[BB*C3], g_s3v[BB*C3];
__device__ float g_flat[TT*BB*C3];
__device__ float g_stcc[BB*C3], g_stcv[BB*C3];
__device__ float g_src[BB*C3], g_srv[BB*C3];
__device__ float g_r[2*BB*C3];
__device__ float g_sfc[BB*128], g_sfv[BB*128];
__device__ float g_w2t[576*C2];
__device__ float g_w3t[1152*C3];
__device__ float g_tcwt[3*C3*C3];
__device__ float g_recwt[C3*C3];
__device__ float g_fc1wt[C3*128];

typedef unsigned long long u64;
__device__ __forceinline__ u64 pk2(float lo, float hi){
    u64 r; asm("mov.b64 %0, {%1,%2};" : "=l"(r) : "f"(lo), "f"(hi)); return r;
}
__device__ __forceinline__ void upk2(u64 v, float &lo, float &hi){
    asm("mov.b64 {%0,%1}, %2;" : "=f"(lo), "=f"(hi) : "l"(v));
}
__device__ __forceinline__ u64 ffma2(u64 a, u64 b, u64 c){
    u64 d; asm("fma.rn.f32x2 %0, %1, %2, %3;" : "=l"(d) : "l"(a), "l"(b), "l"(c)); return d;
}
// CUBA-LIF; state = (cur, veff = vlt*(1-spike))
__device__ __forceinline__ float lifs(float z, float* cp, float* vp){
    float cur = 0.5f*(*cp) + z;
    float vlt = 0.75f*(*vp) + cur;
    bool s = vlt > 0.5f;
    *cp = cur; *vp = s ? 0.0f : vlt;
    return s ? 1.0f : 0.0f;
}

__global__ void k_zero(float* __restrict__ dout){
    int i0 = blockIdx.x*blockDim.x + threadIdx.x, st = gridDim.x*blockDim.x;
    for(int i=i0;i<BB*C1*64;i+=st){ g_s1c[i]=0.f; g_s1v[i]=0.f; }
    for(int i=i0;i<BB*C2*36;i+=st){ g_s2c[i]=0.f; g_s2v[i]=0.f; }
    for(int i=i0;i<BB*C3;i+=st){
        g_s3c[i]=0.f; g_s3v[i]=0.f; g_stcc[i]=0.f; g_stcv[i]=0.f;
        g_src[i]=0.f; g_srv[i]=0.f; g_r[i]=0.f; g_r[BB*C3+i]=0.f;
    }
    for(int i=i0;i<BB*128;i+=st){ g_sfc[i]=0.f; g_sfv[i]=0.f; }
    for(int i=i0;i<BB*2;i+=st) dout[i]=0.f;
}

__global__ void k_prep(const float* __restrict__ w2, const float* __restrict__ w3,
                       const float* __restrict__ tcw, const float* __restrict__ recw,
                       const float* __restrict__ fc1w){
    int i0 = blockIdx.x*blockDim.x + threadIdx.x, st = gridDim.x*blockDim.x;
    for(int i=i0;i<C2*576;i+=st){ int co=i/576, k=i-co*576; g_w2t[k*C2+co]=w2[i]; }
    for(int i=i0;i<C3*1152;i+=st){ int co=i/1152, k=i-co*1152; g_w3t[k*C3+co]=w3[i]; }
    for(int i=i0;i<3*C3*C3;i+=st){
        int j=i/(C3*C3), r=i-j*C3*C3, o=r/C3, k=r-o*C3;
        g_tcwt[j*C3*C3 + k*C3 + o]=tcw[i];
    }
    for(int i=i0;i<C3*C3;i+=st){ int o=i/C3, k=i-o*C3; g_recwt[k*C3+o]=recw[i]; }
    for(int i=i0;i<128*C3;i+=st){ int o=i/C3, k=i-o*C3; g_fc1wt[k*128+o]=fc1w[i]; }
}

// ===== fused conv1 + conv2 + LIF + avgpool (unchanged from R5 — verified) =====
#define K2_CH    8
#define K2_CHF   (K2_CH*9*C2)
#define K2_SMEM  (8192*8 + 2*K2_CHF*4)

__global__ __launch_bounds__(256) void k_conv12(const float* __restrict__ x,
                                                const float* __restrict__ w1,
                                                const float* __restrict__ b1,
                                                const float* __restrict__ b2, int t){
    extern __shared__ char smraw[];
    u64*   sc1 = (u64*)smraw;
    float* sw  = (float*)(smraw + 8192*8);
    __shared__ float sx[200];
    int tid = threadIdx.x, b0 = blockIdx.x*2;

    if (tid < 200){
        int im = tid/100, p = tid-100*im;
        sx[tid] = x[((b0+im)*100 + p)*TT + t];
    }
    __syncthreads();
    #pragma unroll 4
    for (int l=0; l<32; l++){
        int i = l*256 + tid;
        int im = i>>12, e = i&4095;
        int c = e>>6, pos = e&63, ii = pos>>3, jj = pos&7;
        float z = __ldg(&b1[c]);
        const float* wp = w1 + c*9;
        const float* xp = sx + im*100 + ii*10 + jj;
        #pragma unroll
        for(int ki=0;ki<3;ki++)
            #pragma unroll
            for(int kj=0;kj<3;kj++)
                z += __ldg(&wp[ki*3+kj]) * xp[ki*10+kj];
        int gidx = ((b0+im)<<12) + e;
        float v = lifs(z, &g_s1c[gidx], &g_s1v[gidx]);
        sc1[i] = pk2(v,v);
    }

    int h   = tid>>7, lt = tid&127;
    int cog = lt>>2, quad = lt&3;
    int co0 = cog*4;
    int oi0 = (quad>>1)*3, oj0 = (quad&1)*3;
    const u64* scb = sc1 + h*4096;

    float4 bb = *(const float4*)&b2[co0];
    u64 acc[2][9];
    {
        u64 p0 = pk2(bb.x,bb.y), p1 = pk2(bb.z,bb.w);
        #pragma unroll
        for(int p=0;p<9;p++){ acc[0][p]=p0; acc[1][p]=p1; }
    }

    float4 pre[9];
    {
        const float4* src = (const float4*)g_w2t + tid;
        #pragma unroll
        for(int j=0;j<9;j++) pre[j] = src[j*256];
    }
    __syncthreads();
    {
        float4* dst = (float4*)sw + tid;
        #pragma unroll
        for(int j=0;j<9;j++) dst[j*256] = pre[j];
    }
    __syncthreads();

    for (int ch=0; ch<64/K2_CH; ch++){
        if (ch < 64/K2_CH - 1){
            const float4* src = (const float4*)g_w2t + (ch+1)*(K2_CHF/4) + tid;
            #pragma unroll
            for(int j=0;j<9;j++) pre[j] = src[j*256];
        }
        const float* wbuf = sw + (ch&1)*K2_CHF;
        #pragma unroll 2
        for (int cl=0; cl<K2_CH; cl++){
            int ci = ch*K2_CH + cl;
            u64 win[25];
            const u64* wr = scb + ci*64 + oi0*8 + oj0;
            #pragma unroll
            for(int di=0;di<5;di++)
                #pragma unroll
                for(int dj=0;dj<5;dj++)
                    win[di*5+dj] = wr[di*8+dj];
            #pragma unroll
            for(int kk=0;kk<9;kk++){
                const int ki = kk/3, kj = kk - ki*3;
                float4 wv = *(const float4*)&wbuf[(cl*9+kk)*C2 + co0];
                u64 w0 = pk2(wv.x,wv.y), w1p = pk2(wv.z,wv.w);
                #pragma unroll
                for(int p=0;p<9;p++){
                    const int pi = p/3, pj = p - pi*3;
                    u64 s = win[(pi+ki)*5 + (pj+kj)];
                    acc[0][p] = ffma2(w0,  s, acc[0][p]);
                    acc[1][p] = ffma2(w1p, s, acc[1][p]);
                }
            }
        }
        if (ch < 64/K2_CH - 1){
            float4* dst = (float4*)(sw + ((ch+1)&1)*K2_CHF) + tid;
            #pragma unroll
            for(int j=0;j<9;j++) dst[j*256] = pre[j];
        }
        __syncthreads();
    }

    float* zbuf = (float*)sc1;
    #pragma unroll
    for(int cp=0;cp<2;cp++)
        #pragma unroll
        for(int p=0;p<9;p++){
            float z0,z1; upk2(acc[cp][p], z0, z1);
            int di=p/3, dj=p-di*3, pidx=(oi0+di)*6 + (oj0+dj);
            zbuf[(h*C2 + co0+2*cp  )*36 + pidx] = z0;
            zbuf[(h*C2 + co0+2*cp+1)*36 + pidx] = z1;
        }
    __syncthreads();
    float* sc2 = sw;
    for(int i=tid;i<2*C2*36;i+=256){
        int gidx = b0*C2*36 + i;
        sc2[i] = lifs(zbuf[i], &g_s2c[gidx], &g_s2v[gidx]);
    }
    __syncthreads();
    for(int i=tid;i<2*C2*9;i+=256){
        int hh = i/(C2*9), rem = i - hh*(C2*9);
        int c = rem/9, pp = rem-c*9, pi = pp/3, pj = pp-pi*3;
        const float* s2 = sc2 + (hh*C2 + c)*36;
        g_pool[b0*C2*9 + i] = 0.25f*(s2[(2*pi)*6+2*pj] + s2[(2*pi)*6+2*pj+1]
                                   + s2[(2*pi+1)*6+2*pj] + s2[(2*pi+1)*6+2*pj+1]);
    }
}

// ===== conv3: K=1152 GEMV + LIF =====
// 128 blocks = 64 img-quads x 2 co-halves. 256 threads = 128 co x 2 K-halves.
// Thread owns 1 co, all 4 images; weights loaded once, spikes via broadcast LDS.128.
__global__ __launch_bounds__(256) void k_conv3(const float* __restrict__ b3, int t){
    __shared__ __align__(16) float sp_t[1152*4];   // [k][img]
    __shared__ __align__(16) float red[128*4];
    int blk = blockIdx.x, b0 = (blk>>1)*4, ch = blk&1, tid = threadIdx.x;
    #pragma unroll
    for(int img=0;img<4;img++){
        const float* src = g_pool + (b0+img)*1152;
        for(int i=tid;i<1152;i+=256) sp_t[i*4+img] = src[i];
    }
    __syncthreads();
    int co_l = tid&127, kh = tid>>7;
    int co = ch*128 + co_l;
    const float* w  = g_w3t + (kh*576)*C3 + co;
    const float* st = sp_t + kh*576*4;
    float a0=0.f,a1=0.f,a2=0.f,a3=0.f;
    for(int k0=0;k0<576;k0+=16){
        float wv[16];
        #pragma unroll
        for(int j=0;j<16;j++) wv[j] = w[(k0+j)*C3];
        #pragma unroll
        for(int j=0;j<16;j++){
            float4 sv = *(const float4*)(st + (k0+j)*4);
            a0+=wv[j]*sv.x; a1+=wv[j]*sv.y; a2+=wv[j]*sv.z; a3+=wv[j]*sv.w;
        }
    }
    if (kh==1) *(float4*)&red[co_l*4] = make_float4(a0,a1,a2,a3);
    __syncthreads();
    if (kh==0){
        float4 rv = *(const float4*)&red[co_l*4];
        float bz = __ldg(&b3[co]);
        float av[4] = {a0+rv.x+bz, a1+rv.y+bz, a2+rv.z+bz, a3+rv.w+bz};
        #pragma unroll
        for(int img=0;img<4;img++){
            int gi = (b0+img)*C3 + co;
            g_flat[t*BB*C3 + gi] = lifs(av[img], &g_s3c[gi], &g_s3v[gi]);
        }
    }
}

// ===== fused tail: tc + LIF, recurrent + LIF, fc1 + LIF, fc2 accum =====
// 64 blocks x 4 images, 256 threads = 256 output columns; spikes transposed [k][img].
__global__ __launch_bounds__(256) void k_tail(const float* __restrict__ tcb,
                       const float* __restrict__ recb,
                       const float* __restrict__ fc1b, const float* __restrict__ fc2w,
                       const float* __restrict__ tsw, float* __restrict__ dout,
                       int t, int nb){
    __shared__ __align__(16) float sf_t[3][1024];
    __shared__ __align__(16) float r_t[1024];
    __shared__ __align__(16) float sr_t[1024];
    __shared__ __align__(16) float f1_t[512];
    __shared__ __align__(16) float red2[512];
    int b0 = blockIdx.x*4, tid = threadIdx.x;
    for(int j=0;j<nb;j++){
        const float* fl = g_flat + (t-(nb-1)+j)*BB*C3 + b0*C3;
        #pragma unroll
        for(int img=0;img<4;img++) sf_t[j][tid*4+img] = fl[img*C3+tid];
    }
    {
        const float* rp = g_r + ((t+1)&1)*BB*C3 + b0*C3;
        #pragma unroll
        for(int img=0;img<4;img++) r_t[tid*4+img] = rp[img*C3+tid];
    }
    __syncthreads();
    int co = tid;
    // ---- temporal conv ----
    float a[4];
    {
        float bsum = 0.f;
        for(int j=0;j<nb;j++) bsum += tcb[j*C3+co];
        a[0]=a[1]=a[2]=a[3]=bsum;
    }
    for(int j=0;j<nb;j++){
        const float* w  = g_tcwt + j*C3*C3 + co;
        const float* st = sf_t[j];
        for(int k0=0;k0<C3;k0+=16){
            float wv[16];
            #pragma unroll
            for(int jj=0;jj<16;jj++) wv[jj] = w[(k0+jj)*C3];
            #pragma unroll
            for(int jj=0;jj<16;jj++){
                float4 sv = *(const float4*)(st + (k0+jj)*4);
                a[0]+=wv[jj]*sv.x; a[1]+=wv[jj]*sv.y; a[2]+=wv[jj]*sv.z; a[3]+=wv[jj]*sv.w;
            }
        }
    }
    float tcs[4];
    #pragma unroll
    for(int img=0;img<4;img++){
        int gi = (b0+img)*C3 + co;
        tcs[img] = lifs(a[img], &g_stcc[gi], &g_stcv[gi]);
    }
    // ---- recurrent ----
    {
        float rb = recb[co];
        #pragma unroll
        for(int img=0;img<4;img++) a[img] = tcs[img] + rb;
        const float* w = g_recwt + co;
        for(int k0=0;k0<C3;k0+=16){
            float wv[16];
            #pragma unroll
            for(int jj=0;jj<16;jj++) wv[jj] = w[(k0+jj)*C3];
            #pragma unroll
            for(int jj=0;jj<16;jj++){
                float4 sv = *(const float4*)(r_t + (k0+jj)*4);
                a[0]+=wv[jj]*sv.x; a[1]+=wv[jj]*sv.y; a[2]+=wv[jj]*sv.z; a[3]+=wv[jj]*sv.w;
            }
        }
    }
    {
        float rs[4];
        #pragma unroll
        for(int img=0;img<4;img++){
            int gi = (b0+img)*C3 + co;
            rs[img] = lifs(a[img], &g_src[gi], &g_srv[gi]);
            g_r[(t&1)*BB*C3 + gi] = rs[img];
        }
        *(float4*)&sr_t[co*4] = make_float4(rs[0],rs[1],rs[2],rs[3]);
    }
    __syncthreads();
    // ---- fc1 (128 out, K split in halves across tid>>7) ----
    int o = tid&127, kh = tid>>7;
    float f[4]={0.f,0.f,0.f,0.f};
    {
        const float* w  = g_fc1wt + (kh*128)*128 + o;
        const float* st = sr_t + kh*128*4;
        for(int k0=0;k0<128;k0+=16){
            float wv[16];
            #pragma unroll
            for(int jj=0;jj<16;jj++) wv[jj] = w[(k0+jj)*128];
            #pragma unroll
            for(int jj=0;jj<16;jj++){
                float4 sv = *(const float4*)(st + (k0+jj)*4);
                f[0]+=wv[jj]*sv.x; f[1]+=wv[jj]*sv.y; f[2]+=wv[jj]*sv.z; f[3]+=wv[jj]*sv.w;
            }
        }
    }
    if (kh==1) *(float4*)&red2[o*4] = make_float4(f[0],f[1],f[2],f[3]);
    __syncthreads();
    if (kh==0){
        float4 rv = *(const float4*)&red2[o*4];
        float fb = fc1b[o];
        float fv[4] = {f[0]+rv.x+fb, f[1]+rv.y+fb, f[2]+rv.z+fb, f[3]+rv.w+fb};
        float fo[4];
        #pragma unroll
        for(int img=0;img<4;img++){
            int gi = (b0+img)*128 + o;
            fo[img] = lifs(fv[img], &g_sfc[gi], &g_sfv[gi]);
        }
        *(float4*)&f1_t[o*4] = make_float4(fo[0],fo[1],fo[2],fo[3]);
    }
    __syncthreads();
    // ---- fc2 accumulate ----
    if (tid < 8){
        int im = tid>>1, oo = tid&1;
        float s = 0.f;
        #pragma unroll 8
        for(int k=0;k<128;k++) s += f1_t[k*4+im]*fc2w[oo*128+k];
        dout[(b0+im)*2+oo] += s*tsw[t];
    }
}

extern "C" void kernel_launch(void* const* d_in, const int* in_sizes, int n_in,
                              void* d_out, int out_size){
    const float* x    = (const float*)d_in[0];
    const float* w1   = (const float*)d_in[1];
    const float* b1   = (const float*)d_in[2];
    const float* w2   = (const float*)d_in[3];
    const float* b2   = (const float*)d_in[4];
    const float* w3   = (const float*)d_in[5];
    const float* b3   = (const float*)d_in[6];
    const float* tcw  = (const float*)d_in[7];
    const float* tcb  = (const float*)d_in[8];
    const float* recw = (const float*)d_in[9];
    const float* recb = (const float*)d_in[10];
    const float* fc1w = (const float*)d_in[11];
    const float* fc1b = (const float*)d_in[12];
    const float* fc2w = (const float*)d_in[13];
    const float* tsw  = (const float*)d_in[14];
    float* out = (float*)d_out;

    cudaFuncSetAttribute(k_conv12, cudaFuncAttributeMaxDynamicSharedMemorySize, K2_SMEM);

    k_zero<<<256,256>>>(out);
    k_prep<<<256,256>>>(w2, w3, tcw, recw, fc1w);
    for (int t=0; t<TT; t++){
        int nb = t+1 < 3 ? t+1 : 3;
        k_conv12<<<128,256,K2_SMEM>>>(x, w1, b1, b2, t);
        k_conv3<<<128,256>>>(b3, t);
        k_tail<<<64,256>>>(tcb, recb, fc1b, fc2w, tsw, out, t, nb);
    }
}